// round 9
// baseline (speedup 1.0000x reference)
#include <cuda_runtime.h>

#define B 8
#define M 2048
#define N 2048
#define IN 256
#define TM 8
#define TN 1024
#define NCHUNK 16
#define DCHUNK 8    // 128 / NCHUNK

// ---- scratch (allocation-free: __device__ globals) ----
__device__ float g_vp[2][IN][NCHUNK];   // partial folds, [which][col][chunk]
__device__ float g_consts[2];
__device__ float g_s0[B * M];       // s0 + const0
__device__ float g_ls0[B * M];      // logsig(z0)
__device__ float g_lsn0[B * M];     // logsig(-z0)
__device__ float g_s1b[B * N];      // s1 + const1 (bc folded)
__device__ float g_ls1[B * N];      // logsig(z1)
__device__ float g_lsn1[B * N];     // logsig(-z1)

// Negated coefficients of deg-6 poly for ln(1+u), u in [0,1]
#define PC0 (-1.79e-6f)
#define PC1 (-0.99984773f)
#define PC2 ( 0.49737292f)
#define PC3 (-0.31574592f)
#define PC4 ( 0.19035072f)
#define PC5 (-0.08269517f)
#define PC6 ( 0.01741517f)
#define NEG_L2E (-1.4426950408889634f)

__device__ __forceinline__ float ex2_(float x) {
    float r; asm("ex2.approx.f32 %0, %1;" : "=f"(r) : "f"(x)); return r;
}

__device__ __forceinline__ float lsig(float x) {   // reference-accurate, tiny arrays only
    return fminf(x, 0.0f) - __logf(1.0f + __expf(-fabsf(x)));
}

// fast scalar log-sigmoid + q:  min(c,0) - log1p(exp(-|c|)) + q
__device__ __forceinline__ float lsig_fast(float c, float q) {
    float u = ex2_(fabsf(c) * NEG_L2E);          // exp(-|c|), 1 MUFU
    float p = fmaf(PC6, u, PC5);
    p = fmaf(p, u, PC4);
    p = fmaf(p, u, PC3);
    p = fmaf(p, u, PC2);
    p = fmaf(p, u, PC1);
    p = fmaf(p, u, PC0);                         // p = -log1p(u)
    return fminf(c, 0.0f) + p + q;
}

// ---- kernel 0: partial fold of projection weights through Wc ----
// grid (NCHUNK, 2): block (c, which) folds d = c*DCHUNK .. +DCHUNK-1.
// Loads fully coalesced (256 threads sweep one 1KB W row per d).
__global__ void prep_kernel(const float* __restrict__ W0, const float* __restrict__ b0,
                            const float* __restrict__ W1, const float* __restrict__ b1,
                            const float* __restrict__ Wc, const float* __restrict__ bc) {
    int i = threadIdx.x;             // 0..255 (output column)
    int chunk = blockIdx.x;
    int which = blockIdx.y;
    const float* W  = which ? W1 : W0;
    const float* wc = Wc + which * 128;

    float a = 0.f;
    int d0 = chunk * DCHUNK;
    #pragma unroll
    for (int dd = 0; dd < DCHUNK; dd++) {
        int d = d0 + dd;
        a += W[d * IN + i] * wc[d];
    }
    g_vp[which][i][chunk] = a;

    // chunk-0 blocks also compute the bias constants (one warp each)
    if (chunk == 0 && i < 32) {
        const float* bias = which ? b1 : b0;
        float c = 0.f;
        #pragma unroll
        for (int d = i; d < 128; d += 32) c += bias[d] * wc[d];
        #pragma unroll
        for (int o = 16; o; o >>= 1) c += __shfl_down_sync(0xffffffffu, c, o);
        if (i == 0) g_consts[which] = which ? (c + bc[0]) : c;
    }
}

// ---- kernel 1: per-row dot products; one warp per row ----
__global__ void rows_kernel(const float* __restrict__ d0, const float* __restrict__ d1,
                            const float* __restrict__ Wm, const float* __restrict__ bm) {
    int which = blockIdx.y;
    const float* desc = which ? d1 : d0;
    int warp = threadIdx.x >> 5, lane = threadIdx.x & 31;
    int row = blockIdx.x * 8 + warp;

    // reduce the NCHUNK partial folds into smem v[256] (4x LDG.128 per thread)
    __shared__ float sh_v[IN];
    {
        const float4* vp4 = (const float4*)g_vp[which][threadIdx.x];
        float a = 0.f;
        #pragma unroll
        for (int c = 0; c < NCHUNK / 4; c++) {
            float4 v = vp4[c];
            a += v.x + v.y + v.z + v.w;
        }
        sh_v[threadIdx.x] = a;
    }
    __syncthreads();

    const float4* dp = (const float4*)(desc + (size_t)row * IN);
    const float4* vp = (const float4*)sh_v;
    const float4* wp = (const float4*)Wm;

    float as = 0.f, az = 0.f;
    #pragma unroll
    for (int j = 0; j < 2; j++) {
        int k = lane + j * 32;
        float4 dv = dp[k];
        float4 vv = vp[k];
        float4 wv = wp[k];
        as += dv.x * vv.x + dv.y * vv.y + dv.z * vv.z + dv.w * vv.w;
        az += dv.x * wv.x + dv.y * wv.y + dv.z * wv.z + dv.w * wv.w;
    }
    #pragma unroll
    for (int o = 16; o; o >>= 1) {
        as += __shfl_down_sync(0xffffffffu, as, o);
        az += __shfl_down_sync(0xffffffffu, az, o);
    }
    if (lane == 0) {
        float z = az + bm[0];
        if (which == 0) {
            g_s0[row]   = as + g_consts[0];
            g_ls0[row]  = lsig(z);
            g_lsn0[row] = lsig(-z);
        } else {
            g_s1b[row]  = as + g_consts[1];
            g_ls1[row]  = lsig(z);
            g_lsn1[row] = lsig(-z);
        }
    }
}

// ---- kernel 2: fused probs + corres + right edge + bottom row ----
// probs mapping: thread t -> cols n0+t+j*256 (coalesced scalar STG; row stride 2049).
// corres mapping: thread t -> cols n0+4t..4t+3 (STG.128; row stride 2048).
__global__ void __launch_bounds__(256) fused_kernel(float* __restrict__ probs,
                                                    float* __restrict__ corres,
                                                    int has_corres) {
    int b  = blockIdx.z;
    int m0 = blockIdx.y * TM;
    int n0 = blockIdx.x * TN;
    int tx = threadIdx.x;

    __shared__ float sh_s0[TM];
    __shared__ float sh_ls0[TM];
    if (tx < TM) {
        int r = b * M + m0 + tx;
        sh_s0[tx]  = g_s0[r];
        sh_ls0[tx] = g_ls0[r];
    }

    float s1v[4], ls1v[4];
    #pragma unroll
    for (int j = 0; j < 4; j++) {
        int n = n0 + tx + j * 256;
        s1v[j]  = g_s1b[b * N + n];
        ls1v[j] = g_ls1[b * N + n];
    }
    float4 s1c = *(const float4*)(g_s1b + b * N + n0 + 4 * tx);
    __syncthreads();

    size_t pbase = (size_t)b * (M + 1) * (N + 1);
    float*  prow = probs + pbase + (size_t)m0 * (N + 1) + n0 + tx;
    float4* crow = (float4*)(corres + (size_t)b * M * N + (size_t)m0 * N + n0) + tx;
    const bool wc = (has_corres != 0);

    #pragma unroll
    for (int r = 0; r < TM; r++) {
        float s0 = sh_s0[r];
        float l0 = sh_ls0[r];

        if (wc) {
            *crow = make_float4(s0 + s1c.x, s0 + s1c.y, s0 + s1c.z, s0 + s1c.w);
            crow += N / 4;
        }

        prow[0]   = lsig_fast(s0 + s1v[0], l0 + ls1v[0]);
        prow[256] = lsig_fast(s0 + s1v[1], l0 + ls1v[1]);
        prow[512] = lsig_fast(s0 + s1v[2], l0 + ls1v[2]);
        prow[768] = lsig_fast(s0 + s1v[3], l0 + ls1v[3]);
        prow += (N + 1);
    }

    // fused right-edge column: probs[b, m0..m0+TM-1, N] = logsig(-z0)
    if (blockIdx.x == (N / TN - 1) && tx < TM) {
        probs[pbase + (size_t)(m0 + tx) * (N + 1) + N] = g_lsn0[b * M + m0 + tx];
    }

    // fused bottom row (+ corner): blocks in the last row stripe write row M
    if (blockIdx.y == (M / TM - 1)) {
        float* brow = probs + pbase + (size_t)M * (N + 1);
        #pragma unroll
        for (int j = 0; j < 4; j++) {
            int n = n0 + tx + j * 256;
            brow[n] = g_lsn1[b * N + n];
        }
        if (blockIdx.x == (N / TN - 1) && tx == 0) brow[N] = 0.0f;
    }
}

extern "C" void kernel_launch(void* const* d_in, const int* in_sizes, int n_in,
                              void* d_out, int out_size) {
    const float* desc0 = (const float*)d_in[0];
    const float* desc1 = (const float*)d_in[1];
    const float* W0    = (const float*)d_in[2];
    const float* b0    = (const float*)d_in[3];
    const float* W1    = (const float*)d_in[4];
    const float* b1    = (const float*)d_in[5];
    const float* Wm    = (const float*)d_in[6];
    const float* bm    = (const float*)d_in[7];
    const float* Wc    = (const float*)d_in[8];
    const float* bc    = (const float*)d_in[9];

    float* out = (float*)d_out;
    long long probs_elems  = (long long)B * (M + 1) * (N + 1);
    long long corres_elems = (long long)B * M * N;
    int has_corres = ((long long)out_size >= probs_elems + corres_elems) ? 1 : 0;
    float* probs  = out;
    float* corres = out + probs_elems;

    prep_kernel<<<dim3(NCHUNK, 2), 256>>>(W0, b0, W1, b1, Wc, bc);
    rows_kernel<<<dim3(B * M / 8, 2), 256>>>(desc0, desc1, Wm, bm);
    fused_kernel<<<dim3(N / TN, M / TM, B), 256>>>(probs, corres, has_corres);
}